// round 5
// baseline (speedup 1.0000x reference)
#include <cuda_runtime.h>
#include <cstdint>
#include <math.h>

#define BB   128
#define TIN  256
#define DIN  64
#define HH   1024
#define G4   4096
#define TOUT 128
#define DOUT 128

#define K1   (HH + DIN)   // 1088
#define NKC1 (K1 / 8)     // 136
#define NKC2 (HH / 8)     // 128

// -------------------- device scratch (static, allowed) --------------------
__device__ float g_W1p [512 * NKC1 * 64];   // [Wh1;Wi1] permuted to B-frag order, tf32-rounded
__device__ float g_W2p [512 * NKC2 * 64];   // Wh2 permuted
__device__ float g_Wi2p[512 * NKC2 * 64];   // Wi2 permuted
__device__ float g_Wlp [ 16 * NKC2 * 64];   // Wlin permuted
__device__ float g_xr  [BB * TIN * DIN];    // tf32-rounded x
__device__ float g_Hbuf[2 * BB * HH];       // ping-pong hidden state (tf32-rounded values)
__device__ float g_C   [BB * HH];           // cell state, fp32
__device__ float g_XG2 [BB * G4];           // t_last @ Wi2 + b2 (constant over layer-2 time)
__device__ float g_HS2 [TOUT * BB * HH];    // layer-2 hidden states [t][b][h], tf32-rounded

// -------------------- helpers --------------------
__device__ __forceinline__ float tf32r(float x) {
    uint32_t u;
    asm("cvt.rna.tf32.f32 %0, %1;" : "=r"(u) : "f"(x));
    return __uint_as_float(u);
}

__device__ __forceinline__ float sigf(float x) { return 1.0f / (1.0f + expf(-x)); }

__device__ __forceinline__ void mma8(float c[4], const uint32_t a[4], uint32_t b0, uint32_t b1) {
    asm volatile(
        "mma.sync.aligned.m16n8k8.row.col.f32.tf32.tf32.f32 "
        "{%0,%1,%2,%3}, {%4,%5,%6,%7}, {%8,%9}, {%0,%1,%2,%3};"
        : "+f"(c[0]), "+f"(c[1]), "+f"(c[2]), "+f"(c[3])
        : "r"(a[0]), "r"(a[1]), "r"(a[2]), "r"(a[3]), "r"(b0), "r"(b1));
}

// -------------------- prep kernels --------------------
// Permute W[k][n] (row-major, leading dim ldsrc) into B-fragment order:
//   dst[((nt*nkc + kc)*32 + lane)*2 + reg] = tf32( W[kc*8 + reg*4 + lane%4][nt*8 + lane/4] )
// For which==0 (layer1 concat), rows k >= HH come from Wx (= Wi1).
__global__ void permW_kernel(const float* __restrict__ Wh, const float* __restrict__ Wx,
                             int which, int nkc, int ldsrc, int total) {
    int i = blockIdx.x * blockDim.x + threadIdx.x;
    if (i >= total) return;
    float* dst = (which == 0) ? g_W1p : (which == 1) ? g_W2p : (which == 2) ? g_Wi2p : g_Wlp;
    int reg  = i & 1;
    int lane = (i >> 1) & 31;
    int kc   = (i >> 6) % nkc;
    int nt   = i / (nkc * 64);
    int k = kc * 8 + reg * 4 + (lane & 3);
    int n = nt * 8 + (lane >> 2);
    float v = (k < HH) ? Wh[k * ldsrc + n] : Wx[(k - HH) * ldsrc + n];
    dst[i] = tf32r(v);
}

__global__ void roundx_kernel(const float* __restrict__ x, int total) {
    int i = blockIdx.x * blockDim.x + threadIdx.x;
    if (i < total) g_xr[i] = tf32r(x[i]);
}

__global__ void zero_kernel() {
    int i = blockIdx.x * blockDim.x + threadIdx.x;
    if (i < BB * HH) { g_Hbuf[i] = 0.0f; g_C[i] = 0.0f; }
}

// -------------------- main GEMM / step kernel --------------------
// MODE 0: layer-1 LSTM step   (K=1088 = [h | x_t], epilogue = gates + b1)
// MODE 1: layer-2 LSTM step   (K=1024, epilogue = gates + XG2, store hs2)
// MODE 2: XG2 = t_last @ Wi2 + b2   (K=1024, raw write)
// MODE 3: out = HS2 @ Wlin + blin   (K=1024, grid (TOUT, 4))
template<int MODE>
__global__ void __launch_bounds__(256)
gemm_kernel(const float* __restrict__ bias, int t, int rd, float* __restrict__ out) {
    constexpr int KTOT = (MODE == 0) ? K1 : HH;
    constexpr int NKC  = KTOT / 8;
    constexpr int NC   = KTOT / 32;

    __shared__ float sA[2][4096];   // 32 KB double-buffered A chunk (128 rows x 32 k), frag layout

    const int tid  = threadIdx.x;
    const int w    = tid >> 5;
    const int lane = tid & 31;
    const int cta  = blockIdx.x;

    const float* Aptr;
    const float* Wp;
    if (MODE == 3) { Aptr = g_HS2 + blockIdx.x * (BB * HH); Wp = g_Wlp; }
    else {
        Aptr = g_Hbuf + rd * (BB * HH);
        Wp = (MODE == 0) ? g_W1p : (MODE == 1) ? g_W2p : g_Wi2p;
    }

    float acc[4][4];
    #pragma unroll
    for (int q = 0; q < 4; ++q)
        #pragma unroll
        for (int r = 0; r < 4; ++r) acc[q][r] = 0.0f;

    // Stage one 128x32 A chunk into smem in fragment-ready (XOR-swizzled) layout.
    auto stage = [&](int c, float* dstbuf) {
        #pragma unroll
        for (int j = 0; j < 4; ++j) {
            int s  = tid + j * 256;      // 0..1023 float4 slots
            int m  = s >> 3;             // batch row 0..127
            int kq = s & 7;              // k-quad within chunk
            int k0 = c * 32 + kq * 4;
            float4 v;
            if (MODE == 0 && k0 >= HH)
                v = *(const float4*)(g_xr + (m * TIN + t) * DIN + (k0 - HH));
            else
                v = *(const float4*)(Aptr + m * HH + k0);
            int kk  = kq >> 1;                          // local k8 index 0..3
            int reg = (kq & 1) * 2 + ((m >> 3) & 1);    // a-fragment register index
            int hi3 = (m & 7) ^ kq;                     // bank-conflict swizzle
            *(float4*)(dstbuf + kk * 1024 + ((m >> 4) * 4 + reg) * 32 + hi3 * 4) = v;
        }
    };

    stage(0, sA[0]);
    __syncthreads();

    for (int c = 0; c < NC; ++c) {
        const float* buf = sA[c & 1];
        if (c + 1 < NC) stage(c + 1, sA[(c + 1) & 1]);

        // Prefetch all 16 B fragments for this chunk (decouples LDG latency from MMA chain)
        float2 bfr[4][4];
        #pragma unroll
        for (int kk = 0; kk < 4; ++kk) {
            int kc = c * 4 + kk;
            #pragma unroll
            for (int q = 0; q < 4; ++q) {
                int nt = (MODE == 3) ? (blockIdx.y * 4 + q) : (cta + q * 128);
                bfr[kk][q] = *(const float2*)(Wp + ((nt * NKC + kc) * 32 + lane) * 2);
            }
        }

        #pragma unroll
        for (int kk = 0; kk < 4; ++kk) {
            uint32_t a[4];
            #pragma unroll
            for (int r = 0; r < 4; ++r) {
                int hi3 = (lane >> 2) ^ (kk * 2 + (r >> 1));
                a[r] = __float_as_uint(buf[kk * 1024 + (w * 4 + r) * 32 + hi3 * 4 + (lane & 3)]);
            }
            #pragma unroll
            for (int q = 0; q < 4; ++q)
                mma8(acc[q], a, __float_as_uint(bfr[kk][q].x), __float_as_uint(bfr[kk][q].y));
        }
        __syncthreads();
    }

    // -------------------- epilogue --------------------
    #pragma unroll
    for (int cr = 0; cr < 4; ++cr) {
        int m    = w * 16 + (lane >> 2) + ((cr >> 1) << 3);  // batch row
        int jloc = (lane & 3) * 2 + (cr & 1);                // column within 8-wide tile

        if (MODE == 3) {
            #pragma unroll
            for (int q = 0; q < 4; ++q) {
                int d = blockIdx.y * 32 + q * 8 + jloc;
                out[m * (TOUT * DOUT) + blockIdx.x * DOUT + d] = acc[q][cr] + bias[d];
            }
        } else if (MODE == 2) {
            #pragma unroll
            for (int q = 0; q < 4; ++q) {
                int n = q * HH + cta * 8 + jloc;
                g_XG2[m * G4 + n] = acc[q][cr] + bias[n];
            }
        } else {
            int j = cta * 8 + jloc;   // hidden column owned by this CTA (race-free)
            float gi = acc[0][cr], gf = acc[1][cr], gg = acc[2][cr], go = acc[3][cr];
            if (MODE == 0) {
                gi += bias[j];          gf += bias[HH + j];
                gg += bias[2 * HH + j]; go += bias[3 * HH + j];
            } else {
                gi += g_XG2[m * G4 + j];          gf += g_XG2[m * G4 + HH + j];
                gg += g_XG2[m * G4 + 2 * HH + j]; go += g_XG2[m * G4 + 3 * HH + j];
            }
            float cold = g_C[m * HH + j];
            float cn = sigf(gf) * cold + sigf(gi) * tanhf(gg);
            float hn = sigf(go) * tanhf(cn);
            g_C[m * HH + j] = cn;
            float hr = tf32r(hn);
            g_Hbuf[(rd ^ 1) * (BB * HH) + m * HH + j] = hr;
            if (MODE == 1) g_HS2[t * (BB * HH) + m * HH + j] = hr;
        }
    }
}

// -------------------- launch --------------------
extern "C" void kernel_launch(void* const* d_in, const int* in_sizes, int n_in,
                              void* d_out, int out_size) {
    const float* x    = (const float*)d_in[0];
    const float* Wi1  = (const float*)d_in[1];
    const float* Wh1  = (const float*)d_in[2];
    const float* b1   = (const float*)d_in[3];
    const float* Wi2  = (const float*)d_in[4];
    const float* Wh2  = (const float*)d_in[5];
    const float* b2   = (const float*)d_in[6];
    const float* Wlin = (const float*)d_in[7];
    const float* blin = (const float*)d_in[8];
    float* out = (float*)d_out;

    // ---- prep (recomputed every call; deterministic) ----
    {
        int n;
        n = 512 * NKC1 * 64;
        permW_kernel<<<(n + 255) / 256, 256>>>(Wh1, Wi1, 0, NKC1, G4, n);
        n = 512 * NKC2 * 64;
        permW_kernel<<<(n + 255) / 256, 256>>>(Wh2, nullptr, 1, NKC2, G4, n);
        permW_kernel<<<(n + 255) / 256, 256>>>(Wi2, nullptr, 2, NKC2, G4, n);
        n = 16 * NKC2 * 64;
        permW_kernel<<<(n + 255) / 256, 256>>>(Wlin, nullptr, 3, NKC2, DOUT, n);
        n = BB * TIN * DIN;
        roundx_kernel<<<(n + 255) / 256, 256>>>(x, n);
        zero_kernel<<<(BB * HH + 255) / 256, 256>>>();
    }

    int rd = 0;
    // ---- layer 1: 256 recurrent steps ----
    for (int t = 0; t < TIN; ++t) {
        gemm_kernel<0><<<128, 256>>>(b1, t, rd, nullptr);
        rd ^= 1;
    }
    // ---- xg2 = t_last @ Wi2 + b2 (once) ----
    gemm_kernel<2><<<128, 256>>>(b2, 0, rd, nullptr);
    // ---- layer 2: 128 recurrent steps (state h,c carries over) ----
    for (int t = 0; t < TOUT; ++t) {
        gemm_kernel<1><<<128, 256>>>(nullptr, t, rd, nullptr);
        rd ^= 1;
    }
    // ---- final projection: out[b,t,:] = hs2[t,b,:] @ Wlin + blin ----
    gemm_kernel<3><<<dim3(TOUT, 4), 256>>>(blin, 0, 0, out);
}